// round 6
// baseline (speedup 1.0000x reference)
#include <cuda_runtime.h>
#include <cuda_fp16.h>
#include <cstdint>

// ---------------------------------------------------------------------------
// Problem constants
// ---------------------------------------------------------------------------
#define NSAMP 4096
#define DIM   1024     // IN == HID == DIM_T
#define LAYERS 4
#define GROWS (LAYERS*4*DIM)       // 16384 stacked gate rows
#define NSTEP (NSAMP*LAYERS)       // 16384 sequential steps
#define NCTA  147                  // scan CTAs; CTA k owns h[7k .. 7k+7)

// ---------------------------------------------------------------------------
// Scratch (static device globals; no runtime allocation)
// ---------------------------------------------------------------------------
__device__ float g_PE [(size_t)NSAMP*DIM];
__device__ float g_T1 [(size_t)NSAMP*DIM];
__device__ float g_EMB[(size_t)NSAMP*DIM];
__device__ float g_XP [(size_t)NSAMP*DIM];
__device__ float g_R  [(size_t)GROWS*NSAMP];   // 256 MB: R[row, i]
__device__ float g_H  [(size_t)NSAMP*DIM];
__device__ float g_BS [GROWS];
// h exchange: ONE 16B slot per CTA = {7 x fp16 h, u16 tag}, double-buffered
// by step parity: buffer b holds steps with (g&1)==b.
__device__ uint4 g_hx[2*NCTA];

// ---------------------------------------------------------------------------
// 16B volatile vector ld/st (single L2 transaction carrying data + tag)
// ---------------------------------------------------------------------------
__device__ __forceinline__ uint4 ldv4(const uint4* p) {
    uint4 v;
    asm volatile("ld.volatile.global.v4.u32 {%0,%1,%2,%3}, [%4];"
                 : "=r"(v.x), "=r"(v.y), "=r"(v.z), "=r"(v.w) : "l"(p) : "memory");
    return v;
}
__device__ __forceinline__ void stv4(uint4* p, uint4 v) {
    asm volatile("st.volatile.global.v4.u32 [%0], {%1,%2,%3,%4};"
                 :: "l"(p), "r"(v.x), "r"(v.y), "r"(v.z), "r"(v.w) : "memory");
}

__device__ __forceinline__ float tanh_hw(float x) {
    float y;
    asm("tanh.approx.f32 %0, %1;" : "=f"(y) : "f"(x));
    return y;
}
__device__ __forceinline__ float sigmoid_hw(float x) {
    return 0.5f + 0.5f * tanh_hw(0.5f * x);
}

// ---------------------------------------------------------------------------
// Small prologue kernels
// ---------------------------------------------------------------------------
__global__ void pe_kernel(const int* __restrict__ ts, float* __restrict__ PE) {
    int i = blockIdx.x;
    float t = (float)ts[i];
    for (int d = threadIdx.x; d < DIM/2; d += blockDim.x) {
        float f = expf((float)d * (-9.210340371976184f / (float)(DIM/2 - 1)));
        float a = t * f;
        PE[(size_t)i*DIM + d]          = sinf(a);
        PE[(size_t)i*DIM + DIM/2 + d]  = cosf(a);
    }
}

__global__ void bias_kernel(const float* __restrict__ bih, const float* __restrict__ bhh,
                            float* __restrict__ out) {
    int idx = blockIdx.x*blockDim.x + threadIdx.x;
    if (idx < GROWS) out[idx] = bih[idx] + bhh[idx];
}

__global__ void reset_kernel() {
    int idx = blockIdx.x*blockDim.x + threadIdx.x;
    if (idx < 2*NCTA) g_hx[idx] = make_uint4(0u, 0u, 0u, 0u);  // tag 0, h = 0
}

// ---------------------------------------------------------------------------
// Generic NT GEMM (unchanged from R5): C = A@B^T (+biases/add/silu)
// ---------------------------------------------------------------------------
__global__ __launch_bounds__(256, 2)
void gemm_nt(const float* __restrict__ A, const float* __restrict__ B,
             float* __restrict__ C, int M, int N, int K,
             const float* __restrict__ biasM, const float* __restrict__ biasN,
             const float* __restrict__ addMN, int do_silu)
{
    const int BM = 128, BK = 16;
    __shared__ float As[2][16][128+8];
    __shared__ float Bs[2][16][128+8];

    const int tid = threadIdx.x;
    const int m0 = blockIdx.y * BM, n0 = blockIdx.x * BM;
    const int tx = tid & 15, ty = tid >> 4;

    float4 aF[2], bF[2];

    #pragma unroll
    for (int i = 0; i < 2; i++) {
        int f = tid + i*256;
        int row = f >> 2, c4 = (f & 3) * 4;
        aF[i] = *(const float4*)&A[(size_t)(m0+row)*K + c4];
        bF[i] = *(const float4*)&B[(size_t)(n0+row)*K + c4];
    }
    #pragma unroll
    for (int i = 0; i < 2; i++) {
        int f = tid + i*256;
        int row = f >> 2, c4 = (f & 3) * 4;
        As[0][c4+0][row] = aF[i].x; As[0][c4+1][row] = aF[i].y;
        As[0][c4+2][row] = aF[i].z; As[0][c4+3][row] = aF[i].w;
        Bs[0][c4+0][row] = bF[i].x; Bs[0][c4+1][row] = bF[i].y;
        Bs[0][c4+2][row] = bF[i].z; Bs[0][c4+3][row] = bF[i].w;
    }
    __syncthreads();

    float acc[8][8];
    #pragma unroll
    for (int i = 0; i < 8; i++)
        #pragma unroll
        for (int j = 0; j < 8; j++) acc[i][j] = 0.f;

    const int nk = K / BK;
    for (int kt = 0; kt < nk; kt++) {
        const int cur = kt & 1;
        if (kt + 1 < nk) {
            int k0 = (kt+1)*BK;
            #pragma unroll
            for (int i = 0; i < 2; i++) {
                int f = tid + i*256;
                int row = f >> 2, c4 = (f & 3) * 4;
                aF[i] = *(const float4*)&A[(size_t)(m0+row)*K + k0 + c4];
                bF[i] = *(const float4*)&B[(size_t)(n0+row)*K + k0 + c4];
            }
        }
        #pragma unroll
        for (int k = 0; k < BK; k++) {
            float a[8], b[8];
            *(float4*)&a[0] = *(const float4*)&As[cur][k][ty*8];
            *(float4*)&a[4] = *(const float4*)&As[cur][k][ty*8+4];
            *(float4*)&b[0] = *(const float4*)&Bs[cur][k][tx*8];
            *(float4*)&b[4] = *(const float4*)&Bs[cur][k][tx*8+4];
            #pragma unroll
            for (int i = 0; i < 8; i++)
                #pragma unroll
                for (int j = 0; j < 8; j++)
                    acc[i][j] += a[i] * b[j];
        }
        if (kt + 1 < nk) {
            const int nxt = cur ^ 1;
            #pragma unroll
            for (int i = 0; i < 2; i++) {
                int f = tid + i*256;
                int row = f >> 2, c4 = (f & 3) * 4;
                As[nxt][c4+0][row] = aF[i].x; As[nxt][c4+1][row] = aF[i].y;
                As[nxt][c4+2][row] = aF[i].z; As[nxt][c4+3][row] = aF[i].w;
                Bs[nxt][c4+0][row] = bF[i].x; Bs[nxt][c4+1][row] = bF[i].y;
                Bs[nxt][c4+2][row] = bF[i].z; Bs[nxt][c4+3][row] = bF[i].w;
            }
            __syncthreads();
        }
    }

    #pragma unroll
    for (int i = 0; i < 8; i++) {
        int m = m0 + ty*8 + i;
        float bm = biasM ? biasM[m] : 0.f;
        #pragma unroll
        for (int j = 0; j < 8; j++) {
            int n = n0 + tx*8 + j;
            float v = acc[i][j] + bm;
            if (biasN) v += biasN[n];
            if (addMN) v += addMN[(size_t)m*N + n];
            if (do_silu) v = v / (1.f + __expf(-v));
            C[(size_t)m*N + n] = v;
        }
    }
}

// ---------------------------------------------------------------------------
// Persistent sequential-scan kernel. 147 CTAs x 256 threads (8 warps).
// Warp w: gate q = w>>1, K-half kh = w&1. 7 rows per warp over 512 halves.
// ---------------------------------------------------------------------------
#define SCAN_TPB  256
#define WS_HALFS  (LAYERS*28*1024)            // 114688 halves
#define WS_BYTES  (WS_HALFS*2)                // 229376 B
#define HSM_BYTES 2176                        // 1024 halves + poller-overrun pad
#define SCAN_SMEM (WS_BYTES + HSM_BYTES + (56+56)*4)

__global__ __launch_bounds__(SCAN_TPB, 1)
void scan_kernel(const float* __restrict__ Whh, const float* __restrict__ R,
                 float* __restrict__ Hbuf)
{
    extern __shared__ unsigned char smem[];
    __half* ws    = (__half*)smem;                        // [(l*28+rl)*1024 + k]
    __half* h_sm  = (__half*)(smem + WS_BYTES);           // [1024] (+pad)
    float*  gpart = (float*)(smem + WS_BYTES + HSM_BYTES);// [2][28]
    float*  ga    = gpart + 56;                           // [2][28]

    const int cta = blockIdx.x, tid = threadIdx.x;
    const int j0  = cta * 7;
    const int nj  = (j0 + 7 <= DIM) ? 7 : (DIM - j0);     // last CTA: 2

    // ---- fill SMEM weights (fp16, dense rows: ws[(l*28 + q*7+u)*1024 + k])
    for (int p = tid; p < WS_HALFS; p += SCAN_TPB) {
        int rowblk = p >> 10;                   // l*28 + rl
        int l  = rowblk / 28, rl = rowblk - l*28;
        int k  = p & 1023;
        int q = rl / 7, u = rl - q*7;
        float v = 0.f;
        if (u < nj)
            v = Whh[((size_t)l*4*DIM + q*DIM + j0 + u)*DIM + k];
        ws[p] = __float2half(v);
    }
    __syncthreads();

    const int w = tid >> 5, lane = tid & 31;
    const int wq = w >> 1;          // gate index 0..3
    const int kh = w & 1;           // K half
    float cst = 0.f;                // c state (warp0 lane u)

    // ---- R prefetch bookkeeping (one step ahead), threads 0..27
    int pf_q = 0, pf_u = 0;
    bool pf_act = (tid < 28);
    if (pf_act) { pf_q = tid / 7; pf_u = tid - pf_q*7; pf_act = (pf_u < nj); }
    float a_cur = 0.f;
    if (pf_act)   // step g=1: i=0, l=0
        a_cur = R[((size_t)(pf_q*DIM + j0 + pf_u))*NSAMP + 0];

    #pragma unroll 1
    for (int g = 1; g <= NSTEP; ++g) {
        const int s = g - 1;
        const int i = s >> 2, l = s & 3;

        // ---- issue next step's R prefetch (hides a full step of DRAM latency)
        float a_nxt = 0.f;
        if (pf_act && g < NSTEP) {
            int i2 = g >> 2, l2 = g & 3;
            a_nxt = R[((size_t)(l2*4*DIM + pf_q*DIM + j0 + pf_u))*NSAMP + i2];
        }
        if (tid < 28) ga[(g & 1)*28 + tid] = a_cur;

        // ---- poll: thread t<147 spins on slot t (one dependent 16B load)
        if (tid < NCTA) {
            const uint4* p = g_hx + (s & 1)*NCTA + tid;
            uint4 v;
            do { v = ldv4(p); } while ((v.w >> 16) < (unsigned)s);
            __half* d = h_sm + tid*7;
            d[0] = __ushort_as_half((unsigned short)(v.x & 0xffff));
            d[1] = __ushort_as_half((unsigned short)(v.x >> 16));
            d[2] = __ushort_as_half((unsigned short)(v.y & 0xffff));
            d[3] = __ushort_as_half((unsigned short)(v.y >> 16));
            d[4] = __ushort_as_half((unsigned short)(v.z & 0xffff));
            d[5] = __ushort_as_half((unsigned short)(v.z >> 16));
            d[6] = __ushort_as_half((unsigned short)(v.w & 0xffff));
        }
        __syncthreads();   // B1

        // ---- load h half (512 halves for this warp) as half2 registers
        const uint4* h4 = (const uint4*)h_sm;
        uint4 ha = h4[kh*64 + lane];
        uint4 hb = h4[kh*64 + 32 + lane];
        __half2 hh[8];
        *(uint4*)&hh[0] = ha;
        *(uint4*)&hh[4] = hb;

        // ---- 7 rows (gate wq), fp16 products, two chains flushed to fp32
        float part[7];
        #pragma unroll
        for (int t = 0; t < 7; t++) {
            const int rl = wq*7 + t;
            const uint4* w4 = (const uint4*)(ws + (((size_t)l*28 + rl) << 10));
            uint4 wa = w4[kh*64 + lane];
            uint4 wb = w4[kh*64 + 32 + lane];
            __half2 ww[8];
            *(uint4*)&ww[0] = wa;
            *(uint4*)&ww[4] = wb;
            __half2 acA = __hmul2(ww[0], hh[0]);
            __half2 acB = __hmul2(ww[4], hh[4]);
            #pragma unroll
            for (int p2 = 1; p2 < 4; p2++) {
                acA = __hfma2(ww[p2],   hh[p2],   acA);
                acB = __hfma2(ww[p2+4], hh[p2+4], acB);
            }
            float2 fA = __half22float2(acA);
            float2 fB = __half22float2(acB);
            part[t] = (fA.x + fA.y) + (fB.x + fB.y);
        }
        #pragma unroll
        for (int t = 0; t < 7; t++) {
            float v = part[t];
            v += __shfl_xor_sync(0xffffffffu, v, 16);
            v += __shfl_xor_sync(0xffffffffu, v, 8);
            v += __shfl_xor_sync(0xffffffffu, v, 4);
            v += __shfl_xor_sync(0xffffffffu, v, 2);
            v += __shfl_xor_sync(0xffffffffu, v, 1);
            if (lane == 0) gpart[kh*28 + wq*7 + t] = v;
        }
        __syncthreads();   // B2

        // ---- gate math + single-slot publish (warp 0)
        if (w == 0) {
            float h = 0.f;
            if (lane < nj) {
                const float* gav = ga + (g & 1)*28;
                float gi = gpart[lane]      + gpart[28 + lane]      + gav[lane];
                float gf = gpart[7 + lane]  + gpart[28 + 7 + lane]  + gav[7 + lane];
                float gg = gpart[14 + lane] + gpart[28 + 14 + lane] + gav[14 + lane];
                float go = gpart[21 + lane] + gpart[28 + 21 + lane] + gav[21 + lane];
                float I = sigmoid_hw(gi);
                float F = sigmoid_hw(gf);
                float G = tanh_hw(gg);
                cst = F * cst + I * G;
                float O = sigmoid_hw(go);
                h = O * tanh_hw(cst);
            }
            unsigned hu = (unsigned)__half_as_ushort(__float2half(h));
            unsigned v0 = hu | (__shfl_sync(0xffffffffu, hu, 1) << 16);
            unsigned v1 = __shfl_sync(0xffffffffu, hu, 2) |
                          (__shfl_sync(0xffffffffu, hu, 3) << 16);
            unsigned v2 = __shfl_sync(0xffffffffu, hu, 4) |
                          (__shfl_sync(0xffffffffu, hu, 5) << 16);
            unsigned v3 = __shfl_sync(0xffffffffu, hu, 6) |
                          ((unsigned)g << 16);
            if (lane == 0)
                stv4(&g_hx[(g & 1)*NCTA + cta], make_uint4(v0, v1, v2, v3));
            if (lane < nj && l == 3)
                Hbuf[(size_t)i*DIM + j0 + lane] = h;
        }
        a_cur = a_nxt;
        // no trailing barrier: next step's poll self-synchronizes on tags
    }
}

// ---------------------------------------------------------------------------
// Launch
// ---------------------------------------------------------------------------
extern "C" void kernel_launch(void* const* d_in, const int* in_sizes, int n_in,
                              void* d_out, int out_size)
{
    const float* x      = (const float*)d_in[0];
    const int*   ts     = (const int*)  d_in[1];
    const float* proj_w = (const float*)d_in[2];
    const float* proj_b = (const float*)d_in[3];
    const float* te_w1  = (const float*)d_in[4];
    const float* te_b1  = (const float*)d_in[5];
    const float* te_w2  = (const float*)d_in[6];
    const float* te_b2  = (const float*)d_in[7];
    const float* Wih    = (const float*)d_in[8];
    const float* Whh    = (const float*)d_in[9];
    const float* bih    = (const float*)d_in[10];
    const float* bhh    = (const float*)d_in[11];
    const float* lin_w  = (const float*)d_in[12];
    const float* lin_b  = (const float*)d_in[13];
    float* out = (float*)d_out;

    float *PE, *T1, *EMB, *XP, *R, *H, *BS;
    cudaGetSymbolAddress((void**)&PE,  g_PE);
    cudaGetSymbolAddress((void**)&T1,  g_T1);
    cudaGetSymbolAddress((void**)&EMB, g_EMB);
    cudaGetSymbolAddress((void**)&XP,  g_XP);
    cudaGetSymbolAddress((void**)&R,   g_R);
    cudaGetSymbolAddress((void**)&H,   g_H);
    cudaGetSymbolAddress((void**)&BS,  g_BS);

    cudaFuncSetAttribute(scan_kernel, cudaFuncAttributeMaxDynamicSharedMemorySize,
                         SCAN_SMEM);

    // 1) sinusoidal PE
    pe_kernel<<<NSAMP, 128>>>(ts, PE);
    // 2) T1 = silu(PE @ te_w1^T + te_b1)
    gemm_nt<<<dim3(DIM/128, NSAMP/128), 256>>>(PE, te_w1, T1, NSAMP, DIM, DIM,
                                               nullptr, te_b1, nullptr, 1);
    // 3) EMB = T1 @ te_w2^T + te_b2
    gemm_nt<<<dim3(DIM/128, NSAMP/128), 256>>>(T1, te_w2, EMB, NSAMP, DIM, DIM,
                                               nullptr, te_b2, nullptr, 0);
    // 4) XP = x @ proj_w^T + proj_b + EMB
    gemm_nt<<<dim3(DIM/128, NSAMP/128), 256>>>(x, proj_w, XP, NSAMP, DIM, DIM,
                                               nullptr, proj_b, EMB, 0);
    // 5) stacked gate bias
    bias_kernel<<<GROWS/256, 256>>>(bih, bhh, BS);
    // 6) R = Wih_stack @ XP^T + bias   (16384 x 4096 x 1024)
    gemm_nt<<<dim3(NSAMP/128, GROWS/128), 256>>>(Wih, XP, R, GROWS, NSAMP, DIM,
                                                 BS, nullptr, nullptr, 0);
    // 7) reset tagged h slots (graph-replay safe)
    reset_kernel<<<1, 2*NCTA>>>();
    // 8) persistent sequential scan
    scan_kernel<<<NCTA, SCAN_TPB, SCAN_SMEM>>>(Whh, R, H);
    // 9) out = H @ lin_w^T + lin_b
    gemm_nt<<<dim3(DIM/128, NSAMP/128), 256>>>(H, lin_w, out, NSAMP, DIM, DIM,
                                               nullptr, lin_b, nullptr, 0);
}